// round 1
// baseline (speedup 1.0000x reference)
#include <cuda_runtime.h>
#include <math.h>
#include <stdint.h>

#define FULLMASK 0xFFFFFFFFu

// ---------------------------------------------------------------------------
// Mask dtype probe: masks come from jnp bool arrays; harness may store them as
// int32, float32, or raw bytes. mask[0,0] is guaranteed True by the generator
// (msk() sets [:,0]=True). Inspect the first 32-bit word:
//   1           -> int32 masks
//   0x3F800000  -> float32 masks
//   anything else (e.g. packed bytes 01 xx 01 xx) -> uint8 masks
// ---------------------------------------------------------------------------
__device__ int g_maskMode;

__global__ void probe_mask_kernel(const unsigned* m) {
    unsigned w = m[0];
    g_maskMode = (w == 1u) ? 0 : ((w == 0x3F800000u) ? 1 : 2);
}

__device__ __forceinline__ float rdmask(const char* b, int i, int mode) {
    if (mode == 0) return (float)(reinterpret_cast<const int*>(b)[i]);
    if (mode == 1) return reinterpret_cast<const float*>(b)[i];
    return (float)(reinterpret_cast<const unsigned char*>(b)[i]);
}

__device__ __forceinline__ float sigm(float x) { return 1.0f / (1.0f + __expf(-x)); }
__device__ __forceinline__ float2 ld2(const float* p) { return *reinterpret_cast<const float2*>(p); }

// ---------------------------------------------------------------------------
// att_fuse for 4 paths per warp. Lane owns output dims (2*lane, 2*lane+1).
// buf layout: buf[4*k + q] holds cat[k] of path-slot q (k in [0,128)).
// e is updated in place: e += sub * sigmoid(leaky(cat@W1+b1) @ W2 + b2).
// ---------------------------------------------------------------------------
__device__ __forceinline__ void att_fuse4(
    float2 e[4], const float2 sub[4], float* buf,
    const float* sW1, const float* sb1, const float* sW2, float b2, int lane)
{
    const int j0 = 2 * lane;
    *reinterpret_cast<float4*>(&buf[8 * lane])       = make_float4(e[0].x, e[1].x, e[2].x, e[3].x);
    *reinterpret_cast<float4*>(&buf[8 * lane + 4])   = make_float4(e[0].y, e[1].y, e[2].y, e[3].y);
    *reinterpret_cast<float4*>(&buf[256 + 8 * lane])     = make_float4(sub[0].x, sub[1].x, sub[2].x, sub[3].x);
    *reinterpret_cast<float4*>(&buf[256 + 8 * lane + 4]) = make_float4(sub[0].y, sub[1].y, sub[2].y, sub[3].y);
    __syncwarp();

    float2 h[4];
    {
        float2 b = make_float2(sb1[j0], sb1[j0 + 1]);
        #pragma unroll
        for (int q = 0; q < 4; q++) h[q] = b;
    }
    #pragma unroll 4
    for (int k = 0; k < 128; k++) {
        float4 c4 = *reinterpret_cast<const float4*>(&buf[4 * k]);
        float2 w  = *reinterpret_cast<const float2*>(&sW1[(k << 6) + j0]);
        float cs[4] = {c4.x, c4.y, c4.z, c4.w};
        #pragma unroll
        for (int q = 0; q < 4; q++) {
            h[q].x = fmaf(cs[q], w.x, h[q].x);
            h[q].y = fmaf(cs[q], w.y, h[q].y);
        }
    }
    float part[4];
    float w2x = sW2[j0], w2y = sW2[j0 + 1];
    #pragma unroll
    for (int q = 0; q < 4; q++) {
        float hx = h[q].x > 0.f ? h[q].x : 0.2f * h[q].x;   // leaky_relu 0.2
        float hy = h[q].y > 0.f ? h[q].y : 0.2f * h[q].y;
        part[q] = hx * w2x + hy * w2y;
    }
    #pragma unroll
    for (int off = 16; off > 0; off >>= 1) {
        #pragma unroll
        for (int q = 0; q < 4; q++) part[q] += __shfl_xor_sync(FULLMASK, part[q], off);
    }
    #pragma unroll
    for (int q = 0; q < 4; q++) {
        float wq = sigm(part[q] + b2);
        e[q].x = fmaf(sub[q].x, wq, e[q].x);
        e[q].y = fmaf(sub[q].y, wq, e[q].y);
    }
    __syncwarp();
}

// ---------------------------------------------------------------------------
// One LSTM step for 4 paths per warp.
// Gate j ownership: lane owns j in {64*a + 2*lane + b : a in 0..3, b in 0..1},
// so i/f/g/o for dims (2l, 2l+1) all live in the same lane -> no shuffles for
// the cell update. sWihT/sWhhT are K-major transposed: [k*256 + j].
// ---------------------------------------------------------------------------
__device__ __forceinline__ void lstm_step4(
    float2 h[4], float2 c[4], const float2 x[4], float* buf,
    const float* sWihT, const float* sWhhT, const float* sBsum, int lane)
{
    const int j0 = 2 * lane;
    *reinterpret_cast<float4*>(&buf[8 * lane])       = make_float4(x[0].x, x[1].x, x[2].x, x[3].x);
    *reinterpret_cast<float4*>(&buf[8 * lane + 4])   = make_float4(x[0].y, x[1].y, x[2].y, x[3].y);
    *reinterpret_cast<float4*>(&buf[256 + 8 * lane])     = make_float4(h[0].x, h[1].x, h[2].x, h[3].x);
    *reinterpret_cast<float4*>(&buf[256 + 8 * lane + 4]) = make_float4(h[0].y, h[1].y, h[2].y, h[3].y);
    __syncwarp();

    float2 g[4][4];   // [gate-block a][path q]
    #pragma unroll
    for (int a = 0; a < 4; a++) {
        float2 b = make_float2(sBsum[64 * a + j0], sBsum[64 * a + j0 + 1]);
        #pragma unroll
        for (int q = 0; q < 4; q++) g[a][q] = b;
    }
    #pragma unroll 2
    for (int k = 0; k < 64; k++) {
        float4 xk = *reinterpret_cast<const float4*>(&buf[4 * k]);
        float xs[4] = {xk.x, xk.y, xk.z, xk.w};
        #pragma unroll
        for (int a = 0; a < 4; a++) {
            float2 w = *reinterpret_cast<const float2*>(&sWihT[k * 256 + 64 * a + j0]);
            #pragma unroll
            for (int q = 0; q < 4; q++) {
                g[a][q].x = fmaf(xs[q], w.x, g[a][q].x);
                g[a][q].y = fmaf(xs[q], w.y, g[a][q].y);
            }
        }
    }
    #pragma unroll 2
    for (int k = 0; k < 64; k++) {
        float4 hk = *reinterpret_cast<const float4*>(&buf[256 + 4 * k]);
        float hs[4] = {hk.x, hk.y, hk.z, hk.w};
        #pragma unroll
        for (int a = 0; a < 4; a++) {
            float2 w = *reinterpret_cast<const float2*>(&sWhhT[k * 256 + 64 * a + j0]);
            #pragma unroll
            for (int q = 0; q < 4; q++) {
                g[a][q].x = fmaf(hs[q], w.x, g[a][q].x);
                g[a][q].y = fmaf(hs[q], w.y, g[a][q].y);
            }
        }
    }
    #pragma unroll
    for (int q = 0; q < 4; q++) {
        float ix = sigm(g[0][q].x), iy = sigm(g[0][q].y);
        float fx = sigm(g[1][q].x), fy = sigm(g[1][q].y);
        float gx = tanhf(g[2][q].x), gy = tanhf(g[2][q].y);
        float ox = sigm(g[3][q].x), oy = sigm(g[3][q].y);
        c[q].x = fx * c[q].x + ix * gx;
        c[q].y = fy * c[q].y + iy * gy;
        h[q].x = ox * tanhf(c[q].x);
        h[q].y = oy * tanhf(c[q].y);
    }
    __syncwarp();
}

// ---------------------------------------------------------------------------
// Main kernel: 1 block/SM (smem-limited), 8 warps/block, 4 paths/warp.
// Shared layout (floats):
//   [0,8192)       att_W1            (128x64, row-major, as-is)
//   [8192,24576)   W_ih^T            (64x256, K-major)
//   [24576,40960)  W_hh^T            (64x256, K-major)
//   [40960,45056)  mlp_W1            (64x64, as-is)
//   [45056..]      b1, W2, mlp_b1, mlp_W2, bsum(=b_ih+b_hh), scalars
//   [45584..]      per-warp 512-float broadcast buffers
// ---------------------------------------------------------------------------
__global__ void __launch_bounds__(256, 1)
patent_path_kernel(
    const int* __restrict__ paths,
    const int* __restrict__ pat_fp_idx,   const char* __restrict__ pat_fp_mask,
    const int* __restrict__ pat_ipc_idx,  const char* __restrict__ pat_ipc_mask,
    const int* __restrict__ pat_comp_idx, const char* __restrict__ pat_comp_mask,
    const int* __restrict__ comp_ind_idx, const char* __restrict__ comp_ind_mask,
    const int* __restrict__ comp_pat_idx, const char* __restrict__ comp_pat_mask,
    const float* __restrict__ company_emb, const float* __restrict__ patent_emb,
    const float* __restrict__ fp_emb, const float* __restrict__ ipc_emb,
    const float* __restrict__ ind_emb,
    const float* __restrict__ W_ih, const float* __restrict__ W_hh,
    const float* __restrict__ b_ih, const float* __restrict__ b_hh,
    const float* __restrict__ att_W1, const float* __restrict__ att_b1,
    const float* __restrict__ att_W2, const float* __restrict__ att_b2,
    const float* __restrict__ mlp_W1, const float* __restrict__ mlp_b1,
    const float* __restrict__ mlp_W2, const float* __restrict__ mlp_b2,
    float* __restrict__ out, int P)
{
    extern __shared__ float sm[];
    float* sW1   = sm;            // 8192
    float* sWihT = sm + 8192;     // 16384
    float* sWhhT = sm + 24576;    // 16384
    float* sMlp  = sm + 40960;    // 4096
    float* sb1   = sm + 45056;    // 64
    float* sW2   = sm + 45120;    // 64
    float* sMb1  = sm + 45184;    // 64
    float* sMW2  = sm + 45248;    // 64
    float* sBsum = sm + 45312;    // 256
    float* bufBase = sm + 45584;  // 8 warps * 512

    const int tid = threadIdx.x;

    // Stage weights. W_ih/W_hh are (256,64) row-major used as x @ W^T, so
    // transpose into K-major so lane-consecutive gate reads are conflict-free.
    for (int i = tid; i < 8192; i += 256) sW1[i] = att_W1[i];
    for (int i = tid; i < 4096; i += 256) sMlp[i] = mlp_W1[i];
    for (int i = tid; i < 16384; i += 256) {
        int j = i >> 6, k = i & 63;
        sWihT[k * 256 + j] = W_ih[i];
        sWhhT[k * 256 + j] = W_hh[i];
    }
    if (tid < 64) {
        sb1[tid]  = att_b1[tid];
        sW2[tid]  = att_W2[tid];
        sMb1[tid] = mlp_b1[tid];
        sMW2[tid] = mlp_W2[tid];
    }
    if (tid < 256) sBsum[tid] = b_ih[tid] + b_hh[tid];
    if (tid == 0) { sm[45568] = att_b2[0]; sm[45569] = mlp_b2[0]; }
    __syncthreads();

    const float attB2 = sm[45568];
    const float mlpB2 = sm[45569];
    const int lane = tid & 31;
    const int warpId = tid >> 5;
    float* buf = bufBase + warpId * 512;
    const int j0 = 2 * lane;
    const int mode = g_maskMode;

    const int totalGroups = (P + 3) >> 2;
    const int warpStride = gridDim.x * 8;

    for (int grp = blockIdx.x * 8 + warpId; grp < totalGroups; grp += warpStride) {
        int pid[4];
        #pragma unroll
        for (int q = 0; q < 4; q++) {
            int p = grp * 4 + q;
            pid[q] = p < P ? p : P - 1;
        }

        float2 e0[4], e1[4], e2[4], e3[4], csub[4], psub[4];
        #pragma unroll
        for (int q = 0; q < 4; q++) {
            const int c0 = paths[pid[q] * 4 + 0];
            const int p1 = paths[pid[q] * 4 + 1];
            const int f2 = paths[pid[q] * 4 + 2];
            const int p3 = paths[pid[q] * 4 + 3];
            e0[q] = ld2(company_emb + (size_t)c0 * 64 + j0);
            e1[q] = ld2(patent_emb  + (size_t)p1 * 64 + j0);
            e2[q] = ld2(fp_emb      + (size_t)f2 * 64 + j0);
            e3[q] = ld2(patent_emb  + (size_t)p3 * 64 + j0);

            // company_sub(c0) = company_emb[c0] + (sum ind + sum pat) / (cnt_ind + cnt_pat)
            float ax = 0.f, ay = 0.f, cnt = 0.f;
            #pragma unroll
            for (int t = 0; t < 4; t++) {
                if (rdmask(comp_ind_mask, c0 * 4 + t, mode) != 0.f) {
                    float2 v = ld2(ind_emb + (size_t)comp_ind_idx[c0 * 4 + t] * 64 + j0);
                    ax += v.x; ay += v.y; cnt += 1.f;
                }
            }
            #pragma unroll
            for (int t = 0; t < 16; t++) {
                if (rdmask(comp_pat_mask, c0 * 16 + t, mode) != 0.f) {
                    float2 v = ld2(patent_emb + (size_t)comp_pat_idx[c0 * 16 + t] * 64 + j0);
                    ax += v.x; ay += v.y; cnt += 1.f;
                }
            }
            float inv = 1.f / cnt;
            csub[q] = make_float2(e0[q].x + ax * inv, e0[q].y + ay * inv);

            // patent_sub(p3) = patent_emb[p3] + (sum fp + sum ipc + sum comp) / cnt
            ax = 0.f; ay = 0.f; cnt = 0.f;
            #pragma unroll
            for (int t = 0; t < 2; t++) {
                if (rdmask(pat_fp_mask, p3 * 2 + t, mode) != 0.f) {
                    float2 v = ld2(fp_emb + (size_t)pat_fp_idx[p3 * 2 + t] * 64 + j0);
                    ax += v.x; ay += v.y; cnt += 1.f;
                }
            }
            #pragma unroll
            for (int t = 0; t < 6; t++) {
                if (rdmask(pat_ipc_mask, p3 * 6 + t, mode) != 0.f) {
                    float2 v = ld2(ipc_emb + (size_t)pat_ipc_idx[p3 * 6 + t] * 64 + j0);
                    ax += v.x; ay += v.y; cnt += 1.f;
                }
            }
            #pragma unroll
            for (int t = 0; t < 2; t++) {
                if (rdmask(pat_comp_mask, p3 * 2 + t, mode) != 0.f) {
                    float2 v = ld2(company_emb + (size_t)pat_comp_idx[p3 * 2 + t] * 64 + j0);
                    ax += v.x; ay += v.y; cnt += 1.f;
                }
            }
            inv = 1.f / cnt;
            psub[q] = make_float2(e3[q].x + ax * inv, e3[q].y + ay * inv);
        }

        // Attention fusions (e1, e2 each fused with csub then psub)
        att_fuse4(e1, csub, buf, sW1, sb1, sW2, attB2, lane);
        att_fuse4(e1, psub, buf, sW1, sb1, sW2, attB2, lane);
        att_fuse4(e2, csub, buf, sW1, sb1, sW2, attB2, lane);
        att_fuse4(e2, psub, buf, sW1, sb1, sW2, attB2, lane);

        // LSTM over seq [e0, e1, e2, e3]
        float2 h[4], c[4];
        #pragma unroll
        for (int q = 0; q < 4; q++) { h[q] = make_float2(0.f, 0.f); c[q] = make_float2(0.f, 0.f); }
        lstm_step4(h, c, e0, buf, sWihT, sWhhT, sBsum, lane);
        lstm_step4(h, c, e1, buf, sWihT, sWhhT, sBsum, lane);
        lstm_step4(h, c, e2, buf, sWihT, sWhhT, sBsum, lane);
        lstm_step4(h, c, e3, buf, sWihT, sWhhT, sBsum, lane);

        // MLP head: sigmoid(relu(h @ mlp_W1 + b1) @ mlp_W2 + b2)
        *reinterpret_cast<float4*>(&buf[8 * lane])     = make_float4(h[0].x, h[1].x, h[2].x, h[3].x);
        *reinterpret_cast<float4*>(&buf[8 * lane + 4]) = make_float4(h[0].y, h[1].y, h[2].y, h[3].y);
        __syncwarp();
        float2 hid[4];
        {
            float2 b = make_float2(sMb1[j0], sMb1[j0 + 1]);
            #pragma unroll
            for (int q = 0; q < 4; q++) hid[q] = b;
        }
        #pragma unroll 4
        for (int k = 0; k < 64; k++) {
            float4 hk = *reinterpret_cast<const float4*>(&buf[4 * k]);
            float2 w  = *reinterpret_cast<const float2*>(&sMlp[(k << 6) + j0]);
            float hs[4] = {hk.x, hk.y, hk.z, hk.w};
            #pragma unroll
            for (int q = 0; q < 4; q++) {
                hid[q].x = fmaf(hs[q], w.x, hid[q].x);
                hid[q].y = fmaf(hs[q], w.y, hid[q].y);
            }
        }
        float part[4];
        {
            float w2x = sMW2[j0], w2y = sMW2[j0 + 1];
            #pragma unroll
            for (int q = 0; q < 4; q++) {
                float a = fmaxf(hid[q].x, 0.f);
                float b = fmaxf(hid[q].y, 0.f);
                part[q] = a * w2x + b * w2y;
            }
        }
        #pragma unroll
        for (int off = 16; off > 0; off >>= 1) {
            #pragma unroll
            for (int q = 0; q < 4; q++) part[q] += __shfl_xor_sync(FULLMASK, part[q], off);
        }
        if (lane == 0) {
            #pragma unroll
            for (int q = 0; q < 4; q++) {
                int p = grp * 4 + q;
                if (p < P) out[p] = sigm(part[q] + mlpB2);
            }
        }
        __syncwarp();
    }
}

// ---------------------------------------------------------------------------
// Launch. Input order per metadata (= setup_inputs dict order):
//  0 paths  1 label  2..3 pat_fp idx/mask  4..5 pat_ipc  6..7 pat_comp
//  8..9 comp_ind  10..11 comp_pat  12 company_emb 13 patent_emb 14 fp_emb
//  15 ipc_emb 16 ind_emb  17 W_ih 18 W_hh 19 b_ih 20 b_hh
//  21 att_W1 22 att_b1 23 att_W2 24 att_b2  25 mlp_W1 26 mlp_b1 27 mlp_W2 28 mlp_b2
// ---------------------------------------------------------------------------
extern "C" void kernel_launch(void* const* d_in, const int* in_sizes, int n_in,
                              void* d_out, int out_size)
{
    const int P = in_sizes[0] / 4;
    constexpr size_t SMEM = (size_t)(45584 + 8 * 512) * sizeof(float);  // 198720 B

    cudaFuncSetAttribute(patent_path_kernel,
                         cudaFuncAttributeMaxDynamicSharedMemorySize, (int)SMEM);

    probe_mask_kernel<<<1, 1>>>((const unsigned*)d_in[3]);

    patent_path_kernel<<<148, 256, SMEM>>>(
        (const int*)d_in[0],
        (const int*)d_in[2],  (const char*)d_in[3],
        (const int*)d_in[4],  (const char*)d_in[5],
        (const int*)d_in[6],  (const char*)d_in[7],
        (const int*)d_in[8],  (const char*)d_in[9],
        (const int*)d_in[10], (const char*)d_in[11],
        (const float*)d_in[12], (const float*)d_in[13], (const float*)d_in[14],
        (const float*)d_in[15], (const float*)d_in[16],
        (const float*)d_in[17], (const float*)d_in[18],
        (const float*)d_in[19], (const float*)d_in[20],
        (const float*)d_in[21], (const float*)d_in[22],
        (const float*)d_in[23], (const float*)d_in[24],
        (const float*)d_in[25], (const float*)d_in[26],
        (const float*)d_in[27], (const float*)d_in[28],
        (float*)d_out, P);
}

// round 3
// speedup vs baseline: 1.2368x; 1.2368x over previous
#include <cuda_runtime.h>
#include <math.h>
#include <stdint.h>

#define FULLMASK 0xFFFFFFFFu

// ---------------------------------------------------------------------------
// Mask dtype probe (mask[0,0] is guaranteed True by the generator).
//   1 -> int32, 0x3F800000 -> float32, else packed uint8
// ---------------------------------------------------------------------------
__device__ int g_maskMode;

__global__ void probe_mask_kernel(const unsigned* m) {
    unsigned w = m[0];
    g_maskMode = (w == 1u) ? 0 : ((w == 0x3F800000u) ? 1 : 2);
}

__device__ __forceinline__ float rdmask(const char* b, int i, int mode) {
    if (mode == 0) return (float)(reinterpret_cast<const int*>(b)[i]);
    if (mode == 1) return reinterpret_cast<const float*>(b)[i];
    return (float)(reinterpret_cast<const unsigned char*>(b)[i]);
}

__device__ __forceinline__ float sigm(float x) { return 1.0f / (1.0f + __expf(-x)); }
__device__ __forceinline__ float2 ld2(const float* p) { return *reinterpret_cast<const float2*>(p); }

// ---------------------------------------------------------------------------
// att_fuse for 4 paths per warp. Lane owns output dims (2*lane, 2*lane+1).
// buf layout: buf[4*k + q] holds cat[k] of path-slot q (k in [0,128)).
// ---------------------------------------------------------------------------
__device__ __forceinline__ void att_fuse4(
    float2 e[4], const float2 sub[4], float* buf,
    const float* sW1, const float* sb1, const float* sW2, float b2, int lane)
{
    const int j0 = 2 * lane;
    *reinterpret_cast<float4*>(&buf[8 * lane])       = make_float4(e[0].x, e[1].x, e[2].x, e[3].x);
    *reinterpret_cast<float4*>(&buf[8 * lane + 4])   = make_float4(e[0].y, e[1].y, e[2].y, e[3].y);
    *reinterpret_cast<float4*>(&buf[256 + 8 * lane])     = make_float4(sub[0].x, sub[1].x, sub[2].x, sub[3].x);
    *reinterpret_cast<float4*>(&buf[256 + 8 * lane + 4]) = make_float4(sub[0].y, sub[1].y, sub[2].y, sub[3].y);
    __syncwarp();

    float2 h[4];
    {
        float2 b = make_float2(sb1[j0], sb1[j0 + 1]);
        #pragma unroll
        for (int q = 0; q < 4; q++) h[q] = b;
    }
    #pragma unroll 4
    for (int k = 0; k < 128; k++) {
        float4 c4 = *reinterpret_cast<const float4*>(&buf[4 * k]);
        float2 w  = *reinterpret_cast<const float2*>(&sW1[(k << 6) + j0]);
        float cs[4] = {c4.x, c4.y, c4.z, c4.w};
        #pragma unroll
        for (int q = 0; q < 4; q++) {
            h[q].x = fmaf(cs[q], w.x, h[q].x);
            h[q].y = fmaf(cs[q], w.y, h[q].y);
        }
    }
    float part[4];
    float w2x = sW2[j0], w2y = sW2[j0 + 1];
    #pragma unroll
    for (int q = 0; q < 4; q++) {
        float hx = h[q].x > 0.f ? h[q].x : 0.2f * h[q].x;   // leaky_relu 0.2
        float hy = h[q].y > 0.f ? h[q].y : 0.2f * h[q].y;
        part[q] = hx * w2x + hy * w2y;
    }
    #pragma unroll
    for (int off = 16; off > 0; off >>= 1) {
        #pragma unroll
        for (int q = 0; q < 4; q++) part[q] += __shfl_xor_sync(FULLMASK, part[q], off);
    }
    #pragma unroll
    for (int q = 0; q < 4; q++) {
        float wq = sigm(part[q] + b2);
        e[q].x = fmaf(sub[q].x, wq, e[q].x);
        e[q].y = fmaf(sub[q].y, wq, e[q].y);
    }
    __syncwarp();
}

// ---------------------------------------------------------------------------
// One LSTM step for 4 paths per warp. Lane owns gate dims
// {64*a + 2*lane + b} so the cell update needs no shuffles.
// ---------------------------------------------------------------------------
__device__ __forceinline__ void lstm_step4(
    float2 h[4], float2 c[4], const float2 x[4], float* buf,
    const float* sWihT, const float* sWhhT, const float* sBsum, int lane)
{
    const int j0 = 2 * lane;
    *reinterpret_cast<float4*>(&buf[8 * lane])       = make_float4(x[0].x, x[1].x, x[2].x, x[3].x);
    *reinterpret_cast<float4*>(&buf[8 * lane + 4])   = make_float4(x[0].y, x[1].y, x[2].y, x[3].y);
    *reinterpret_cast<float4*>(&buf[256 + 8 * lane])     = make_float4(h[0].x, h[1].x, h[2].x, h[3].x);
    *reinterpret_cast<float4*>(&buf[256 + 8 * lane + 4]) = make_float4(h[0].y, h[1].y, h[2].y, h[3].y);
    __syncwarp();

    float2 g[4][4];   // [gate-block a][path q]
    #pragma unroll
    for (int a = 0; a < 4; a++) {
        float2 b = make_float2(sBsum[64 * a + j0], sBsum[64 * a + j0 + 1]);
        #pragma unroll
        for (int q = 0; q < 4; q++) g[a][q] = b;
    }
    #pragma unroll 2
    for (int k = 0; k < 64; k++) {
        float4 xk = *reinterpret_cast<const float4*>(&buf[4 * k]);
        float xs[4] = {xk.x, xk.y, xk.z, xk.w};
        #pragma unroll
        for (int a = 0; a < 4; a++) {
            float2 w = *reinterpret_cast<const float2*>(&sWihT[k * 256 + 64 * a + j0]);
            #pragma unroll
            for (int q = 0; q < 4; q++) {
                g[a][q].x = fmaf(xs[q], w.x, g[a][q].x);
                g[a][q].y = fmaf(xs[q], w.y, g[a][q].y);
            }
        }
    }
    #pragma unroll 2
    for (int k = 0; k < 64; k++) {
        float4 hk = *reinterpret_cast<const float4*>(&buf[256 + 4 * k]);
        float hs[4] = {hk.x, hk.y, hk.z, hk.w};
        #pragma unroll
        for (int a = 0; a < 4; a++) {
            float2 w = *reinterpret_cast<const float2*>(&sWhhT[k * 256 + 64 * a + j0]);
            #pragma unroll
            for (int q = 0; q < 4; q++) {
                g[a][q].x = fmaf(hs[q], w.x, g[a][q].x);
                g[a][q].y = fmaf(hs[q], w.y, g[a][q].y);
            }
        }
    }
    #pragma unroll
    for (int q = 0; q < 4; q++) {
        float ix = sigm(g[0][q].x), iy = sigm(g[0][q].y);
        float fx = sigm(g[1][q].x), fy = sigm(g[1][q].y);
        float gx = tanhf(g[2][q].x), gy = tanhf(g[2][q].y);
        float ox = sigm(g[3][q].x), oy = sigm(g[3][q].y);
        c[q].x = fx * c[q].x + ix * gx;
        c[q].y = fy * c[q].y + iy * gy;
        h[q].x = ox * tanhf(c[q].x);
        h[q].y = oy * tanhf(c[q].y);
    }
    __syncwarp();
}

// ---------------------------------------------------------------------------
// Main kernel: 1 block/SM, 16 warps/block (512 threads), 4 paths/warp.
// Shared layout (floats):
//   [0,8192)       att_W1   (128x64)
//   [8192,24576)   W_ih^T   (64x256, K-major)
//   [24576,40960)  W_hh^T   (64x256, K-major)
//   [40960,45056)  mlp_W1   (64x64)
//   [45056..]      b1, W2, mlp_b1, mlp_W2, bsum, scalars
//   [45584..]      per-warp 512-float broadcast buffers (16 warps)
// ---------------------------------------------------------------------------
__global__ void __launch_bounds__(512, 1)
patent_path_kernel(
    const int* __restrict__ paths,
    const int* __restrict__ pat_fp_idx,   const char* __restrict__ pat_fp_mask,
    const int* __restrict__ pat_ipc_idx,  const char* __restrict__ pat_ipc_mask,
    const int* __restrict__ pat_comp_idx, const char* __restrict__ pat_comp_mask,
    const int* __restrict__ comp_ind_idx, const char* __restrict__ comp_ind_mask,
    const int* __restrict__ comp_pat_idx, const char* __restrict__ comp_pat_mask,
    const float* __restrict__ company_emb, const float* __restrict__ patent_emb,
    const float* __restrict__ fp_emb, const float* __restrict__ ipc_emb,
    const float* __restrict__ ind_emb,
    const float* __restrict__ W_ih, const float* __restrict__ W_hh,
    const float* __restrict__ b_ih, const float* __restrict__ b_hh,
    const float* __restrict__ att_W1, const float* __restrict__ att_b1,
    const float* __restrict__ att_W2, const float* __restrict__ att_b2,
    const float* __restrict__ mlp_W1, const float* __restrict__ mlp_b1,
    const float* __restrict__ mlp_W2, const float* __restrict__ mlp_b2,
    float* __restrict__ out, int P)
{
    extern __shared__ float sm[];
    float* sW1   = sm;            // 8192
    float* sWihT = sm + 8192;     // 16384
    float* sWhhT = sm + 24576;    // 16384
    float* sMlp  = sm + 40960;    // 4096
    float* sb1   = sm + 45056;    // 64
    float* sW2   = sm + 45120;    // 64
    float* sMb1  = sm + 45184;    // 64
    float* sMW2  = sm + 45248;    // 64
    float* sBsum = sm + 45312;    // 256
    float* bufBase = sm + 45584;  // 16 warps * 512

    const int tid = threadIdx.x;
    const int NT = 512;

    // Stage weights. W_ih/W_hh transposed to K-major for conflict-free reads.
    for (int i = tid; i < 8192; i += NT) sW1[i] = att_W1[i];
    for (int i = tid; i < 4096; i += NT) sMlp[i] = mlp_W1[i];
    for (int i = tid; i < 16384; i += NT) {
        int j = i >> 6, k = i & 63;
        sWihT[k * 256 + j] = W_ih[i];
        sWhhT[k * 256 + j] = W_hh[i];
    }
    if (tid < 64) {
        sb1[tid]  = att_b1[tid];
        sW2[tid]  = att_W2[tid];
        sMb1[tid] = mlp_b1[tid];
        sMW2[tid] = mlp_W2[tid];
    }
    if (tid < 256) sBsum[tid] = b_ih[tid] + b_hh[tid];
    if (tid == 0) { sm[45568] = att_b2[0]; sm[45569] = mlp_b2[0]; }
    __syncthreads();

    const float attB2 = sm[45568];
    const float mlpB2 = sm[45569];
    const int lane = tid & 31;
    const int warpId = tid >> 5;
    float* buf = bufBase + warpId * 512;
    const int j0 = 2 * lane;
    const int mode = g_maskMode;

    const int totalGroups = (P + 3) >> 2;
    const int warpStride = gridDim.x * 16;

    for (int grp = blockIdx.x * 16 + warpId; grp < totalGroups; grp += warpStride) {
        int pid[4];
        #pragma unroll
        for (int q = 0; q < 4; q++) {
            int p = grp * 4 + q;
            pid[q] = p < P ? p : P - 1;
        }

        float2 e0[4], e1[4], e2[4], e3[4], csub[4], psub[4];
        #pragma unroll
        for (int q = 0; q < 4; q++) {
            const int c0 = paths[pid[q] * 4 + 0];
            const int p1 = paths[pid[q] * 4 + 1];
            const int f2 = paths[pid[q] * 4 + 2];
            const int p3 = paths[pid[q] * 4 + 3];
            e0[q] = ld2(company_emb + (size_t)c0 * 64 + j0);
            e1[q] = ld2(patent_emb  + (size_t)p1 * 64 + j0);
            e2[q] = ld2(fp_emb      + (size_t)f2 * 64 + j0);
            e3[q] = ld2(patent_emb  + (size_t)p3 * 64 + j0);

            // company_sub(c0)
            float ax = 0.f, ay = 0.f, cnt = 0.f;
            #pragma unroll
            for (int t = 0; t < 4; t++) {
                if (rdmask(comp_ind_mask, c0 * 4 + t, mode) != 0.f) {
                    float2 v = ld2(ind_emb + (size_t)comp_ind_idx[c0 * 4 + t] * 64 + j0);
                    ax += v.x; ay += v.y; cnt += 1.f;
                }
            }
            #pragma unroll
            for (int t = 0; t < 16; t++) {
                if (rdmask(comp_pat_mask, c0 * 16 + t, mode) != 0.f) {
                    float2 v = ld2(patent_emb + (size_t)comp_pat_idx[c0 * 16 + t] * 64 + j0);
                    ax += v.x; ay += v.y; cnt += 1.f;
                }
            }
            float inv = 1.f / cnt;
            csub[q] = make_float2(e0[q].x + ax * inv, e0[q].y + ay * inv);

            // patent_sub(p3)
            ax = 0.f; ay = 0.f; cnt = 0.f;
            #pragma unroll
            for (int t = 0; t < 2; t++) {
                if (rdmask(pat_fp_mask, p3 * 2 + t, mode) != 0.f) {
                    float2 v = ld2(fp_emb + (size_t)pat_fp_idx[p3 * 2 + t] * 64 + j0);
                    ax += v.x; ay += v.y; cnt += 1.f;
                }
            }
            #pragma unroll
            for (int t = 0; t < 6; t++) {
                if (rdmask(pat_ipc_mask, p3 * 6 + t, mode) != 0.f) {
                    float2 v = ld2(ipc_emb + (size_t)pat_ipc_idx[p3 * 6 + t] * 64 + j0);
                    ax += v.x; ay += v.y; cnt += 1.f;
                }
            }
            #pragma unroll
            for (int t = 0; t < 2; t++) {
                if (rdmask(pat_comp_mask, p3 * 2 + t, mode) != 0.f) {
                    float2 v = ld2(company_emb + (size_t)pat_comp_idx[p3 * 2 + t] * 64 + j0);
                    ax += v.x; ay += v.y; cnt += 1.f;
                }
            }
            inv = 1.f / cnt;
            psub[q] = make_float2(e3[q].x + ax * inv, e3[q].y + ay * inv);
        }

        // Attention fusions
        att_fuse4(e1, csub, buf, sW1, sb1, sW2, attB2, lane);
        att_fuse4(e1, psub, buf, sW1, sb1, sW2, attB2, lane);
        att_fuse4(e2, csub, buf, sW1, sb1, sW2, attB2, lane);
        att_fuse4(e2, psub, buf, sW1, sb1, sW2, attB2, lane);

        // LSTM over [e0, e1, e2, e3]
        float2 h[4], c[4];
        #pragma unroll
        for (int q = 0; q < 4; q++) { h[q] = make_float2(0.f, 0.f); c[q] = make_float2(0.f, 0.f); }
        lstm_step4(h, c, e0, buf, sWihT, sWhhT, sBsum, lane);
        lstm_step4(h, c, e1, buf, sWihT, sWhhT, sBsum, lane);
        lstm_step4(h, c, e2, buf, sWihT, sWhhT, sBsum, lane);
        lstm_step4(h, c, e3, buf, sWihT, sWhhT, sBsum, lane);

        // MLP head
        *reinterpret_cast<float4*>(&buf[8 * lane])     = make_float4(h[0].x, h[1].x, h[2].x, h[3].x);
        *reinterpret_cast<float4*>(&buf[8 * lane + 4]) = make_float4(h[0].y, h[1].y, h[2].y, h[3].y);
        __syncwarp();
        float2 hid[4];
        {
            float2 b = make_float2(sMb1[j0], sMb1[j0 + 1]);
            #pragma unroll
            for (int q = 0; q < 4; q++) hid[q] = b;
        }
        #pragma unroll 4
        for (int k = 0; k < 64; k++) {
            float4 hk = *reinterpret_cast<const float4*>(&buf[4 * k]);
            float2 w  = *reinterpret_cast<const float2*>(&sMlp[(k << 6) + j0]);
            float hs[4] = {hk.x, hk.y, hk.z, hk.w};
            #pragma unroll
            for (int q = 0; q < 4; q++) {
                hid[q].x = fmaf(hs[q], w.x, hid[q].x);
                hid[q].y = fmaf(hs[q], w.y, hid[q].y);
            }
        }
        float part[4];
        {
            float w2x = sMW2[j0], w2y = sMW2[j0 + 1];
            #pragma unroll
            for (int q = 0; q < 4; q++) {
                float a = fmaxf(hid[q].x, 0.f);
                float b = fmaxf(hid[q].y, 0.f);
                part[q] = a * w2x + b * w2y;
            }
        }
        #pragma unroll
        for (int off = 16; off > 0; off >>= 1) {
            #pragma unroll
            for (int q = 0; q < 4; q++) part[q] += __shfl_xor_sync(FULLMASK, part[q], off);
        }
        if (lane == 0) {
            #pragma unroll
            for (int q = 0; q < 4; q++) {
                int p = grp * 4 + q;
                if (p < P) out[p] = sigm(part[q] + mlpB2);
            }
        }
        __syncwarp();
    }
}

// ---------------------------------------------------------------------------
extern "C" void kernel_launch(void* const* d_in, const int* in_sizes, int n_in,
                              void* d_out, int out_size)
{
    const int P = in_sizes[0] / 4;
    constexpr size_t SMEM = (size_t)(45584 + 16 * 512) * sizeof(float);  // 215104 B

    cudaFuncSetAttribute(patent_path_kernel,
                         cudaFuncAttributeMaxDynamicSharedMemorySize, (int)SMEM);

    probe_mask_kernel<<<1, 1>>>((const unsigned*)d_in[3]);

    patent_path_kernel<<<148, 512, SMEM>>>(
        (const int*)d_in[0],
        (const int*)d_in[2],  (const char*)d_in[3],
        (const int*)d_in[4],  (const char*)d_in[5],
        (const int*)d_in[6],  (const char*)d_in[7],
        (const int*)d_in[8],  (const char*)d_in[9],
        (const int*)d_in[10], (const char*)d_in[11],
        (const float*)d_in[12], (const float*)d_in[13], (const float*)d_in[14],
        (const float*)d_in[15], (const float*)d_in[16],
        (const float*)d_in[17], (const float*)d_in[18],
        (const float*)d_in[19], (const float*)d_in[20],
        (const float*)d_in[21], (const float*)d_in[22],
        (const float*)d_in[23], (const float*)d_in[24],
        (const float*)d_in[25], (const float*)d_in[26],
        (const float*)d_in[27], (const float*)d_in[28],
        (float*)d_out, P);
}

// round 6
// speedup vs baseline: 1.3108x; 1.0599x over previous
#include <cuda_runtime.h>
#include <math.h>
#include <stdint.h>

#define FULLMASK 0xFFFFFFFFu

// ---------------------------------------------------------------------------
// Mask dtype probe (mask[0,0] is guaranteed True by the generator).
//   1 -> int32, 0x3F800000 -> float32, else packed uint8
// ---------------------------------------------------------------------------
__device__ int g_maskMode;

__global__ void probe_mask_kernel(const unsigned* m) {
    unsigned w = m[0];
    g_maskMode = (w == 1u) ? 0 : ((w == 0x3F800000u) ? 1 : 2);
}

__device__ __forceinline__ float rdmask(const char* b, int i, int mode) {
    if (mode == 0) return (float)(reinterpret_cast<const int*>(b)[i]);
    if (mode == 1) return reinterpret_cast<const float*>(b)[i];
    return (float)(reinterpret_cast<const unsigned char*>(b)[i]);
}

__device__ __forceinline__ float sigm(float x) { return 1.0f / (1.0f + __expf(-x)); }
__device__ __forceinline__ float2 ld2(const float* p) { return *reinterpret_cast<const float2*>(p); }

// ---- Blackwell packed-fp32 helpers ----------------------------------------
__device__ __forceinline__ uint64_t pk2(float x, float y) {
    uint64_t r; asm("mov.b64 %0, {%1, %2};" : "=l"(r) : "f"(x), "f"(y)); return r;
}
__device__ __forceinline__ float2 upk2(uint64_t v) {
    float lo, hi; asm("mov.b64 {%0, %1}, %2;" : "=f"(lo), "=f"(hi) : "l"(v));
    return make_float2(lo, hi);
}
__device__ __forceinline__ void ffma2(uint64_t& d, uint64_t a, uint64_t b) {
    asm("fma.rn.f32x2 %0, %1, %2, %0;" : "+l"(d) : "l"(a), "l"(b));
}

// ---------------------------------------------------------------------------
// att_fuse for 4 paths per warp, path-pair packed fp32x2.
// buf[4*k + q] holds cat[k] of path-slot q (k in [0,128)); one broadcast
// ulonglong2 load gives both packed path-pairs for dim k.
// ---------------------------------------------------------------------------
__device__ __forceinline__ void att_fuse4(
    float2 e[4], const float2 sub[4], float* buf,
    const float* sW1, const float* sb1, const float* sW2, float b2, int lane)
{
    const int j0 = 2 * lane;
    *reinterpret_cast<float4*>(&buf[8 * lane])       = make_float4(e[0].x, e[1].x, e[2].x, e[3].x);
    *reinterpret_cast<float4*>(&buf[8 * lane + 4])   = make_float4(e[0].y, e[1].y, e[2].y, e[3].y);
    *reinterpret_cast<float4*>(&buf[256 + 8 * lane])     = make_float4(sub[0].x, sub[1].x, sub[2].x, sub[3].x);
    *reinterpret_cast<float4*>(&buf[256 + 8 * lane + 4]) = make_float4(sub[0].y, sub[1].y, sub[2].y, sub[3].y);
    __syncwarp();

    const float bx = sb1[j0], by = sb1[j0 + 1];
    uint64_t hx01 = pk2(bx, bx), hx23 = hx01;   // dim j0,   paths (0,1) / (2,3)
    uint64_t hy01 = pk2(by, by), hy23 = hy01;   // dim j0+1

    #pragma unroll 4
    for (int k = 0; k < 128; k++) {
        ulonglong2 pp = *reinterpret_cast<const ulonglong2*>(&buf[4 * k]);  // broadcast
        float2 w = *reinterpret_cast<const float2*>(&sW1[(k << 6) + j0]);
        uint64_t wxx = pk2(w.x, w.x);
        uint64_t wyy = pk2(w.y, w.y);
        ffma2(hx01, pp.x, wxx); ffma2(hx23, pp.y, wxx);
        ffma2(hy01, pp.x, wyy); ffma2(hy23, pp.y, wyy);
    }

    float2 a01 = upk2(hx01), a23 = upk2(hx23), b01 = upk2(hy01), b23 = upk2(hy23);
    float hx[4] = {a01.x, a01.y, a23.x, a23.y};
    float hy[4] = {b01.x, b01.y, b23.x, b23.y};
    const float w2x = sW2[j0], w2y = sW2[j0 + 1];
    float part[4];
    #pragma unroll
    for (int q = 0; q < 4; q++) {
        float ax = hx[q] > 0.f ? hx[q] : 0.2f * hx[q];   // leaky_relu 0.2
        float ay = hy[q] > 0.f ? hy[q] : 0.2f * hy[q];
        part[q] = ax * w2x + ay * w2y;
    }
    #pragma unroll
    for (int off = 16; off > 0; off >>= 1) {
        #pragma unroll
        for (int q = 0; q < 4; q++) part[q] += __shfl_xor_sync(FULLMASK, part[q], off);
    }
    #pragma unroll
    for (int q = 0; q < 4; q++) {
        float wq = sigm(part[q] + b2);
        e[q].x = fmaf(sub[q].x, wq, e[q].x);
        e[q].y = fmaf(sub[q].y, wq, e[q].y);
    }
    __syncwarp();
}

// ---------------------------------------------------------------------------
// One LSTM step for 4 paths per warp, dim-pair packed fp32x2.
// g[a][q] packs gate dims (64a+j0, 64a+j0+1); weight dim-pairs load directly
// as b64 from the K-major smem layout. Cell update needs no shuffles.
// ---------------------------------------------------------------------------
__device__ __forceinline__ void lstm_step4(
    float2 h[4], float2 c[4], const float2 x[4], float* buf,
    const float* sWihT, const float* sWhhT, const float* sBsum, int lane)
{
    const int j0 = 2 * lane;
    *reinterpret_cast<float4*>(&buf[8 * lane])       = make_float4(x[0].x, x[1].x, x[2].x, x[3].x);
    *reinterpret_cast<float4*>(&buf[8 * lane + 4])   = make_float4(x[0].y, x[1].y, x[2].y, x[3].y);
    *reinterpret_cast<float4*>(&buf[256 + 8 * lane])     = make_float4(h[0].x, h[1].x, h[2].x, h[3].x);
    *reinterpret_cast<float4*>(&buf[256 + 8 * lane + 4]) = make_float4(h[0].y, h[1].y, h[2].y, h[3].y);
    __syncwarp();

    uint64_t g[4][4];   // [gate-block a][path q], dims packed
    #pragma unroll
    for (int a = 0; a < 4; a++) {
        uint64_t b = *reinterpret_cast<const uint64_t*>(&sBsum[64 * a + j0]);
        #pragma unroll
        for (int q = 0; q < 4; q++) g[a][q] = b;
    }
    #pragma unroll 2
    for (int k = 0; k < 64; k++) {
        float4 xk = *reinterpret_cast<const float4*>(&buf[4 * k]);   // broadcast
        uint64_t x0 = pk2(xk.x, xk.x), x1 = pk2(xk.y, xk.y);
        uint64_t x2 = pk2(xk.z, xk.z), x3 = pk2(xk.w, xk.w);
        #pragma unroll
        for (int a = 0; a < 4; a++) {
            uint64_t w = *reinterpret_cast<const uint64_t*>(&sWihT[k * 256 + 64 * a + j0]);
            ffma2(g[a][0], x0, w); ffma2(g[a][1], x1, w);
            ffma2(g[a][2], x2, w); ffma2(g[a][3], x3, w);
        }
    }
    #pragma unroll 2
    for (int k = 0; k < 64; k++) {
        float4 hk = *reinterpret_cast<const float4*>(&buf[256 + 4 * k]);
        uint64_t x0 = pk2(hk.x, hk.x), x1 = pk2(hk.y, hk.y);
        uint64_t x2 = pk2(hk.z, hk.z), x3 = pk2(hk.w, hk.w);
        #pragma unroll
        for (int a = 0; a < 4; a++) {
            uint64_t w = *reinterpret_cast<const uint64_t*>(&sWhhT[k * 256 + 64 * a + j0]);
            ffma2(g[a][0], x0, w); ffma2(g[a][1], x1, w);
            ffma2(g[a][2], x2, w); ffma2(g[a][3], x3, w);
        }
    }
    #pragma unroll
    for (int q = 0; q < 4; q++) {
        float2 gi = upk2(g[0][q]), gf = upk2(g[1][q]);
        float2 gg = upk2(g[2][q]), go = upk2(g[3][q]);
        float ix = sigm(gi.x), iy = sigm(gi.y);
        float fx = sigm(gf.x), fy = sigm(gf.y);
        float gx = tanhf(gg.x), gy = tanhf(gg.y);
        float ox = sigm(go.x), oy = sigm(go.y);
        c[q].x = fx * c[q].x + ix * gx;
        c[q].y = fy * c[q].y + iy * gy;
        h[q].x = ox * tanhf(c[q].x);
        h[q].y = oy * tanhf(c[q].y);
    }
    __syncwarp();
}

// ---------------------------------------------------------------------------
// Main kernel: 1 block/SM, 16 warps/block (512 threads), 4 paths/warp.
// Shared layout (floats):
//   [0,8192)       att_W1   (128x64)
//   [8192,24576)   W_ih^T   (64x256, K-major)
//   [24576,40960)  W_hh^T   (64x256, K-major)
//   [40960,45056)  mlp_W1   (64x64)
//   [45056..]      b1, W2, mlp_b1, mlp_W2, bsum, scalars
//   [45584..]      per-warp 512-float broadcast buffers (16 warps)
// ---------------------------------------------------------------------------
__global__ void __launch_bounds__(512, 1)
patent_path_kernel(
    const int* __restrict__ paths,
    const int* __restrict__ pat_fp_idx,   const char* __restrict__ pat_fp_mask,
    const int* __restrict__ pat_ipc_idx,  const char* __restrict__ pat_ipc_mask,
    const int* __restrict__ pat_comp_idx, const char* __restrict__ pat_comp_mask,
    const int* __restrict__ comp_ind_idx, const char* __restrict__ comp_ind_mask,
    const int* __restrict__ comp_pat_idx, const char* __restrict__ comp_pat_mask,
    const float* __restrict__ company_emb, const float* __restrict__ patent_emb,
    const float* __restrict__ fp_emb, const float* __restrict__ ipc_emb,
    const float* __restrict__ ind_emb,
    const float* __restrict__ W_ih, const float* __restrict__ W_hh,
    const float* __restrict__ b_ih, const float* __restrict__ b_hh,
    const float* __restrict__ att_W1, const float* __restrict__ att_b1,
    const float* __restrict__ att_W2, const float* __restrict__ att_b2,
    const float* __restrict__ mlp_W1, const float* __restrict__ mlp_b1,
    const float* __restrict__ mlp_W2, const float* __restrict__ mlp_b2,
    float* __restrict__ out, int P)
{
    extern __shared__ float sm[];
    float* sW1   = sm;            // 8192
    float* sWihT = sm + 8192;     // 16384
    float* sWhhT = sm + 24576;    // 16384
    float* sMlp  = sm + 40960;    // 4096
    float* sb1   = sm + 45056;    // 64
    float* sW2   = sm + 45120;    // 64
    float* sMb1  = sm + 45184;    // 64
    float* sMW2  = sm + 45248;    // 64
    float* sBsum = sm + 45312;    // 256
    float* bufBase = sm + 45584;  // 16 warps * 512

    const int tid = threadIdx.x;
    const int NT = 512;

    // Stage weights. W_ih/W_hh transposed to K-major for conflict-free b64 reads.
    for (int i = tid; i < 8192; i += NT) sW1[i] = att_W1[i];
    for (int i = tid; i < 4096; i += NT) sMlp[i] = mlp_W1[i];
    for (int i = tid; i < 16384; i += NT) {
        int j = i >> 6, k = i & 63;
        sWihT[k * 256 + j] = W_ih[i];
        sWhhT[k * 256 + j] = W_hh[i];
    }
    if (tid < 64) {
        sb1[tid]  = att_b1[tid];
        sW2[tid]  = att_W2[tid];
        sMb1[tid] = mlp_b1[tid];
        sMW2[tid] = mlp_W2[tid];
    }
    if (tid < 256) sBsum[tid] = b_ih[tid] + b_hh[tid];
    if (tid == 0) { sm[45568] = att_b2[0]; sm[45569] = mlp_b2[0]; }
    __syncthreads();

    const float attB2 = sm[45568];
    const float mlpB2 = sm[45569];
    const int lane = tid & 31;
    const int warpId = tid >> 5;
    float* buf = bufBase + warpId * 512;
    const int j0 = 2 * lane;
    const int mode = g_maskMode;

    const int totalGroups = (P + 3) >> 2;
    const int warpStride = gridDim.x * 16;

    for (int grp = blockIdx.x * 16 + warpId; grp < totalGroups; grp += warpStride) {
        int pid[4];
        #pragma unroll
        for (int q = 0; q < 4; q++) {
            int p = grp * 4 + q;
            pid[q] = p < P ? p : P - 1;
        }

        float2 e0[4], e1[4], e2[4], e3[4], csub[4], psub[4];
        #pragma unroll
        for (int q = 0; q < 4; q++) {
            const int c0 = paths[pid[q] * 4 + 0];
            const int p1 = paths[pid[q] * 4 + 1];
            const int f2 = paths[pid[q] * 4 + 2];
            const int p3 = paths[pid[q] * 4 + 3];
            e0[q] = ld2(company_emb + (size_t)c0 * 64 + j0);
            e1[q] = ld2(patent_emb  + (size_t)p1 * 64 + j0);
            e2[q] = ld2(fp_emb      + (size_t)f2 * 64 + j0);
            e3[q] = ld2(patent_emb  + (size_t)p3 * 64 + j0);

            // company_sub(c0)
            float ax = 0.f, ay = 0.f, cnt = 0.f;
            #pragma unroll
            for (int t = 0; t < 4; t++) {
                if (rdmask(comp_ind_mask, c0 * 4 + t, mode) != 0.f) {
                    float2 v = ld2(ind_emb + (size_t)comp_ind_idx[c0 * 4 + t] * 64 + j0);
                    ax += v.x; ay += v.y; cnt += 1.f;
                }
            }
            #pragma unroll
            for (int t = 0; t < 16; t++) {
                if (rdmask(comp_pat_mask, c0 * 16 + t, mode) != 0.f) {
                    float2 v = ld2(patent_emb + (size_t)comp_pat_idx[c0 * 16 + t] * 64 + j0);
                    ax += v.x; ay += v.y; cnt += 1.f;
                }
            }
            float inv = 1.f / cnt;
            csub[q] = make_float2(e0[q].x + ax * inv, e0[q].y + ay * inv);

            // patent_sub(p3)
            ax = 0.f; ay = 0.f; cnt = 0.f;
            #pragma unroll
            for (int t = 0; t < 2; t++) {
                if (rdmask(pat_fp_mask, p3 * 2 + t, mode) != 0.f) {
                    float2 v = ld2(fp_emb + (size_t)pat_fp_idx[p3 * 2 + t] * 64 + j0);
                    ax += v.x; ay += v.y; cnt += 1.f;
                }
            }
            #pragma unroll
            for (int t = 0; t < 6; t++) {
                if (rdmask(pat_ipc_mask, p3 * 6 + t, mode) != 0.f) {
                    float2 v = ld2(ipc_emb + (size_t)pat_ipc_idx[p3 * 6 + t] * 64 + j0);
                    ax += v.x; ay += v.y; cnt += 1.f;
                }
            }
            #pragma unroll
            for (int t = 0; t < 2; t++) {
                if (rdmask(pat_comp_mask, p3 * 2 + t, mode) != 0.f) {
                    float2 v = ld2(company_emb + (size_t)pat_comp_idx[p3 * 2 + t] * 64 + j0);
                    ax += v.x; ay += v.y; cnt += 1.f;
                }
            }
            inv = 1.f / cnt;
            psub[q] = make_float2(e3[q].x + ax * inv, e3[q].y + ay * inv);
        }

        // Attention fusions
        att_fuse4(e1, csub, buf, sW1, sb1, sW2, attB2, lane);
        att_fuse4(e1, psub, buf, sW1, sb1, sW2, attB2, lane);
        att_fuse4(e2, csub, buf, sW1, sb1, sW2, attB2, lane);
        att_fuse4(e2, psub, buf, sW1, sb1, sW2, attB2, lane);

        // LSTM over [e0, e1, e2, e3]
        float2 h[4], c[4];
        #pragma unroll
        for (int q = 0; q < 4; q++) { h[q] = make_float2(0.f, 0.f); c[q] = make_float2(0.f, 0.f); }
        lstm_step4(h, c, e0, buf, sWihT, sWhhT, sBsum, lane);
        lstm_step4(h, c, e1, buf, sWihT, sWhhT, sBsum, lane);
        lstm_step4(h, c, e2, buf, sWihT, sWhhT, sBsum, lane);
        lstm_step4(h, c, e3, buf, sWihT, sWhhT, sBsum, lane);

        // MLP head (path-pair packed, like att_fuse)
        *reinterpret_cast<float4*>(&buf[8 * lane])     = make_float4(h[0].x, h[1].x, h[2].x, h[3].x);
        *reinterpret_cast<float4*>(&buf[8 * lane + 4]) = make_float4(h[0].y, h[1].y, h[2].y, h[3].y);
        __syncwarp();
        {
            const float bx = sMb1[j0], by = sMb1[j0 + 1];
            uint64_t hx01 = pk2(bx, bx), hx23 = hx01;
            uint64_t hy01 = pk2(by, by), hy23 = hy01;
            #pragma unroll 4
            for (int k = 0; k < 64; k++) {
                ulonglong2 pp = *reinterpret_cast<const ulonglong2*>(&buf[4 * k]);
                float2 w = *reinterpret_cast<const float2*>(&sMlp[(k << 6) + j0]);
                uint64_t wxx = pk2(w.x, w.x);
                uint64_t wyy = pk2(w.y, w.y);
                ffma2(hx01, pp.x, wxx); ffma2(hx23, pp.y, wxx);
                ffma2(hy01, pp.x, wyy); ffma2(hy23, pp.y, wyy);
            }
            float2 a01 = upk2(hx01), a23 = upk2(hx23), b01 = upk2(hy01), b23 = upk2(hy23);
            float hx[4] = {a01.x, a01.y, a23.x, a23.y};
            float hy[4] = {b01.x, b01.y, b23.x, b23.y};
            const float w2x = sMW2[j0], w2y = sMW2[j0 + 1];
            float part[4];
            #pragma unroll
            for (int q = 0; q < 4; q++) {
                float a = fmaxf(hx[q], 0.f);
                float b = fmaxf(hy[q], 0.f);
                part[q] = a * w2x + b * w2y;
            }
            #pragma unroll
            for (int off = 16; off > 0; off >>= 1) {
                #pragma unroll
                for (int q = 0; q < 4; q++) part[q] += __shfl_xor_sync(FULLMASK, part[q], off);
            }
            if (lane == 0) {
                #pragma unroll
                for (int q = 0; q < 4; q++) {
                    int p = grp * 4 + q;
                    if (p < P) out[p] = sigm(part[q] + mlpB2);
                }
            }
        }
        __syncwarp();
    }
}

// ---------------------------------------------------------------------------
extern "C" void kernel_launch(void* const* d_in, const int* in_sizes, int n_in,
                              void* d_out, int out_size)
{
    const int P = in_sizes[0] / 4;
    constexpr size_t SMEM = (size_t)(45584 + 16 * 512) * sizeof(float);  // 215104 B

    cudaFuncSetAttribute(patent_path_kernel,
                         cudaFuncAttributeMaxDynamicSharedMemorySize, (int)SMEM);

    probe_mask_kernel<<<1, 1>>>((const unsigned*)d_in[3]);

    patent_path_kernel<<<148, 512, SMEM>>>(
        (const int*)d_in[0],
        (const int*)d_in[2],  (const char*)d_in[3],
        (const int*)d_in[4],  (const char*)d_in[5],
        (const int*)d_in[6],  (const char*)d_in[7],
        (const int*)d_in[8],  (const char*)d_in[9],
        (const int*)d_in[10], (const char*)d_in[11],
        (const float*)d_in[12], (const float*)d_in[13], (const float*)d_in[14],
        (const float*)d_in[15], (const float*)d_in[16],
        (const float*)d_in[17], (const float*)d_in[18],
        (const float*)d_in[19], (const float*)d_in[20],
        (const float*)d_in[21], (const float*)d_in[22],
        (const float*)d_in[23], (const float*)d_in[24],
        (const float*)d_in[25], (const float*)d_in[26],
        (const float*)d_in[27], (const float*)d_in[28],
        (float*)d_out, P);
}

// round 8
// speedup vs baseline: 1.4638x; 1.1167x over previous
#include <cuda_runtime.h>
#include <math.h>
#include <stdint.h>

#define FULLMASK 0xFFFFFFFFu

// ---------------------------------------------------------------------------
// Mask dtype probe (mask[0,0] is guaranteed True by the generator).
//   1 -> int32, 0x3F800000 -> float32, else packed uint8
// ---------------------------------------------------------------------------
__device__ int g_maskMode;

__global__ void probe_mask_kernel(const unsigned* m) {
    unsigned w = m[0];
    g_maskMode = (w == 1u) ? 0 : ((w == 0x3F800000u) ? 1 : 2);
}

__device__ __forceinline__ float rdmask(const char* b, int i, int mode) {
    if (mode == 0) return (float)(reinterpret_cast<const int*>(b)[i]);
    if (mode == 1) return reinterpret_cast<const float*>(b)[i];
    return (float)(reinterpret_cast<const unsigned char*>(b)[i]);
}

// Fast sigmoid: rcp.approx(1 + ex2.approx(-x*log2e)). ~1e-7 rel err.
__device__ __forceinline__ float sigm(float x) {
    float e;
    asm("ex2.approx.f32 %0, %1;" : "=f"(e) : "f"(x * -1.4426950408889634f));
    float r;
    asm("rcp.approx.f32 %0, %1;" : "=f"(r) : "f"(e + 1.0f));
    return r;
}
// HW tanh approximation (MUFU), rel err ~1.6e-5.
__device__ __forceinline__ float tanhap(float x) {
    float r; asm("tanh.approx.f32 %0, %1;" : "=f"(r) : "f"(x)); return r;
}
__device__ __forceinline__ float rcpap(float x) {
    float r; asm("rcp.approx.f32 %0, %1;" : "=f"(r) : "f"(x)); return r;
}
__device__ __forceinline__ float2 ld2(const float* p) { return *reinterpret_cast<const float2*>(p); }

// ---- Blackwell packed-fp32 helpers ----------------------------------------
__device__ __forceinline__ uint64_t pk2(float x, float y) {
    uint64_t r; asm("mov.b64 %0, {%1, %2};" : "=l"(r) : "f"(x), "f"(y)); return r;
}
__device__ __forceinline__ float2 upk2(uint64_t v) {
    float lo, hi; asm("mov.b64 {%0, %1}, %2;" : "=f"(lo), "=f"(hi) : "l"(v));
    return make_float2(lo, hi);
}
__device__ __forceinline__ void ffma2(uint64_t& d, uint64_t a, uint64_t b) {
    asm("fma.rn.f32x2 %0, %1, %2, %0;" : "+l"(d) : "l"(a), "l"(b));
}

// ---------------------------------------------------------------------------
// Paired att_fuse: e1 and e2 each fused with the SAME sub, sharing every
// weight load and the sub broadcasts.  4 paths per warp, path-pair packed.
// buf layout (768 floats/warp): [0,256) e1 vals [4k+q], [256,512) e2 vals,
// [512,768) sub vals.
// ---------------------------------------------------------------------------
__device__ __forceinline__ void att_fuse_pair(
    float2 e1[4], float2 e2[4], const float2 sub[4], float* buf,
    const float* sW1, const float* sb1, const float* sW2, float b2, int lane)
{
    const int j0 = 2 * lane;
    *reinterpret_cast<float4*>(&buf[8 * lane])       = make_float4(e1[0].x, e1[1].x, e1[2].x, e1[3].x);
    *reinterpret_cast<float4*>(&buf[8 * lane + 4])   = make_float4(e1[0].y, e1[1].y, e1[2].y, e1[3].y);
    *reinterpret_cast<float4*>(&buf[256 + 8 * lane])     = make_float4(e2[0].x, e2[1].x, e2[2].x, e2[3].x);
    *reinterpret_cast<float4*>(&buf[256 + 8 * lane + 4]) = make_float4(e2[0].y, e2[1].y, e2[2].y, e2[3].y);
    *reinterpret_cast<float4*>(&buf[512 + 8 * lane])     = make_float4(sub[0].x, sub[1].x, sub[2].x, sub[3].x);
    *reinterpret_cast<float4*>(&buf[512 + 8 * lane + 4]) = make_float4(sub[0].y, sub[1].y, sub[2].y, sub[3].y);
    __syncwarp();

    const float bx = sb1[j0], by = sb1[j0 + 1];
    // accumulators: a = cat[e1,sub], b = cat[e2,sub]; x/y = out dims; 01/23 = path pairs
    uint64_t ax01 = pk2(bx, bx), ax23 = ax01, ay01 = pk2(by, by), ay23 = ay01;
    uint64_t bx01 = ax01, bx23 = ax01, by01 = ay01, by23 = ay01;

    // k in [0,64): e-part of cat (differs between the two fusions)
    #pragma unroll 4
    for (int k = 0; k < 64; k++) {
        float2 w = *reinterpret_cast<const float2*>(&sW1[(k << 6) + j0]);
        uint64_t wxx = pk2(w.x, w.x);
        uint64_t wyy = pk2(w.y, w.y);
        ulonglong2 p1 = *reinterpret_cast<const ulonglong2*>(&buf[4 * k]);        // e1 broadcast
        ulonglong2 p2 = *reinterpret_cast<const ulonglong2*>(&buf[256 + 4 * k]);  // e2 broadcast
        ffma2(ax01, p1.x, wxx); ffma2(ax23, p1.y, wxx);
        ffma2(ay01, p1.x, wyy); ffma2(ay23, p1.y, wyy);
        ffma2(bx01, p2.x, wxx); ffma2(bx23, p2.y, wxx);
        ffma2(by01, p2.x, wyy); ffma2(by23, p2.y, wyy);
    }
    // k in [64,128): sub part of cat (SHARED between the two fusions)
    #pragma unroll 4
    for (int k = 64; k < 128; k++) {
        float2 w = *reinterpret_cast<const float2*>(&sW1[(k << 6) + j0]);
        uint64_t wxx = pk2(w.x, w.x);
        uint64_t wyy = pk2(w.y, w.y);
        ulonglong2 ps = *reinterpret_cast<const ulonglong2*>(&buf[512 + 4 * (k - 64)]);
        ffma2(ax01, ps.x, wxx); ffma2(ax23, ps.y, wxx);
        ffma2(ay01, ps.x, wyy); ffma2(ay23, ps.y, wyy);
        ffma2(bx01, ps.x, wxx); ffma2(bx23, ps.y, wxx);
        ffma2(by01, ps.x, wyy); ffma2(by23, ps.y, wyy);
    }

    float2 A01 = upk2(ax01), A23 = upk2(ax23), B01 = upk2(ay01), B23 = upk2(ay23);
    float2 C01 = upk2(bx01), C23 = upk2(bx23), D01 = upk2(by01), D23 = upk2(by23);
    float h1x[4] = {A01.x, A01.y, A23.x, A23.y};
    float h1y[4] = {B01.x, B01.y, B23.x, B23.y};
    float h2x[4] = {C01.x, C01.y, C23.x, C23.y};
    float h2y[4] = {D01.x, D01.y, D23.x, D23.y};

    const float w2x = sW2[j0], w2y = sW2[j0 + 1];
    float p1[4], p2[4];
    #pragma unroll
    for (int q = 0; q < 4; q++) {
        float a1 = h1x[q] > 0.f ? h1x[q] : 0.2f * h1x[q];   // leaky_relu 0.2
        float b1 = h1y[q] > 0.f ? h1y[q] : 0.2f * h1y[q];
        float a2 = h2x[q] > 0.f ? h2x[q] : 0.2f * h2x[q];
        float b2v = h2y[q] > 0.f ? h2y[q] : 0.2f * h2y[q];
        p1[q] = a1 * w2x + b1 * w2y;
        p2[q] = a2 * w2x + b2v * w2y;
    }
    #pragma unroll
    for (int off = 16; off > 0; off >>= 1) {
        #pragma unroll
        for (int q = 0; q < 4; q++) {
            p1[q] += __shfl_xor_sync(FULLMASK, p1[q], off);
            p2[q] += __shfl_xor_sync(FULLMASK, p2[q], off);
        }
    }
    #pragma unroll
    for (int q = 0; q < 4; q++) {
        float w1 = sigm(p1[q] + b2);
        float w2 = sigm(p2[q] + b2);
        e1[q].x = fmaf(sub[q].x, w1, e1[q].x);
        e1[q].y = fmaf(sub[q].y, w1, e1[q].y);
        e2[q].x = fmaf(sub[q].x, w2, e2[q].x);
        e2[q].y = fmaf(sub[q].y, w2, e2[q].y);
    }
    __syncwarp();
}

// ---------------------------------------------------------------------------
// One LSTM step, 4 paths/warp, dim-pair packed. x- and h-contributions merged
// into ONE k-loop for double the independent work per scheduling window.
// ---------------------------------------------------------------------------
__device__ __forceinline__ void lstm_step4(
    float2 h[4], float2 c[4], const float2 x[4], float* buf,
    const float* sWihT, const float* sWhhT, const float* sBsum, int lane)
{
    const int j0 = 2 * lane;
    *reinterpret_cast<float4*>(&buf[8 * lane])       = make_float4(x[0].x, x[1].x, x[2].x, x[3].x);
    *reinterpret_cast<float4*>(&buf[8 * lane + 4])   = make_float4(x[0].y, x[1].y, x[2].y, x[3].y);
    *reinterpret_cast<float4*>(&buf[256 + 8 * lane])     = make_float4(h[0].x, h[1].x, h[2].x, h[3].x);
    *reinterpret_cast<float4*>(&buf[256 + 8 * lane + 4]) = make_float4(h[0].y, h[1].y, h[2].y, h[3].y);
    __syncwarp();

    uint64_t g[4][4];   // [gate-block a][path q], dims packed
    #pragma unroll
    for (int a = 0; a < 4; a++) {
        uint64_t b = *reinterpret_cast<const uint64_t*>(&sBsum[64 * a + j0]);
        #pragma unroll
        for (int q = 0; q < 4; q++) g[a][q] = b;
    }
    #pragma unroll 2
    for (int k = 0; k < 64; k++) {
        float4 xk = *reinterpret_cast<const float4*>(&buf[4 * k]);         // x broadcast
        float4 hk = *reinterpret_cast<const float4*>(&buf[256 + 4 * k]);   // h broadcast
        uint64_t x0 = pk2(xk.x, xk.x), x1 = pk2(xk.y, xk.y);
        uint64_t x2 = pk2(xk.z, xk.z), x3 = pk2(xk.w, xk.w);
        uint64_t h0 = pk2(hk.x, hk.x), h1 = pk2(hk.y, hk.y);
        uint64_t h2 = pk2(hk.z, hk.z), h3 = pk2(hk.w, hk.w);
        #pragma unroll
        for (int a = 0; a < 4; a++) {
            uint64_t wi = *reinterpret_cast<const uint64_t*>(&sWihT[k * 256 + 64 * a + j0]);
            uint64_t wh = *reinterpret_cast<const uint64_t*>(&sWhhT[k * 256 + 64 * a + j0]);
            ffma2(g[a][0], x0, wi); ffma2(g[a][1], x1, wi);
            ffma2(g[a][2], x2, wi); ffma2(g[a][3], x3, wi);
            ffma2(g[a][0], h0, wh); ffma2(g[a][1], h1, wh);
            ffma2(g[a][2], h2, wh); ffma2(g[a][3], h3, wh);
        }
    }
    #pragma unroll
    for (int q = 0; q < 4; q++) {
        float2 gi = upk2(g[0][q]), gf = upk2(g[1][q]);
        float2 gg = upk2(g[2][q]), go = upk2(g[3][q]);
        float ix = sigm(gi.x), iy = sigm(gi.y);
        float fx = sigm(gf.x), fy = sigm(gf.y);
        float gx = tanhap(gg.x), gy = tanhap(gg.y);
        float ox = sigm(go.x), oy = sigm(go.y);
        c[q].x = fx * c[q].x + ix * gx;
        c[q].y = fy * c[q].y + iy * gy;
        h[q].x = ox * tanhap(c[q].x);
        h[q].y = oy * tanhap(c[q].y);
    }
    __syncwarp();
}

// ---------------------------------------------------------------------------
// Main kernel: 1 block/SM, 16 warps (512 thr), 4 paths/warp.
// Shared (floats): [0,8192) att_W1 | [8192,24576) W_ih^T | [24576,40960) W_hh^T
// | [40960,45056) mlp_W1 | small vectors | [45584..) 16 x 768 per-warp bufs.
// Total 57872 floats = 231488 B (fits the 232448 B sm_100a cap).
// ---------------------------------------------------------------------------
__global__ void __launch_bounds__(512, 1)
patent_path_kernel(
    const int* __restrict__ paths,
    const int* __restrict__ pat_fp_idx,   const char* __restrict__ pat_fp_mask,
    const int* __restrict__ pat_ipc_idx,  const char* __restrict__ pat_ipc_mask,
    const int* __restrict__ pat_comp_idx, const char* __restrict__ pat_comp_mask,
    const int* __restrict__ comp_ind_idx, const char* __restrict__ comp_ind_mask,
    const int* __restrict__ comp_pat_idx, const char* __restrict__ comp_pat_mask,
    const float* __restrict__ company_emb, const float* __restrict__ patent_emb,
    const float* __restrict__ fp_emb, const float* __restrict__ ipc_emb,
    const float* __restrict__ ind_emb,
    const float* __restrict__ W_ih, const float* __restrict__ W_hh,
    const float* __restrict__ b_ih, const float* __restrict__ b_hh,
    const float* __restrict__ att_W1, const float* __restrict__ att_b1,
    const float* __restrict__ att_W2, const float* __restrict__ att_b2,
    const float* __restrict__ mlp_W1, const float* __restrict__ mlp_b1,
    const float* __restrict__ mlp_W2, const float* __restrict__ mlp_b2,
    float* __restrict__ out, int P)
{
    extern __shared__ float sm[];
    float* sW1   = sm;            // 8192
    float* sWihT = sm + 8192;     // 16384
    float* sWhhT = sm + 24576;    // 16384
    float* sMlp  = sm + 40960;    // 4096
    float* sb1   = sm + 45056;    // 64
    float* sW2   = sm + 45120;    // 64
    float* sMb1  = sm + 45184;    // 64
    float* sMW2  = sm + 45248;    // 64
    float* sBsum = sm + 45312;    // 256
    float* bufBase = sm + 45584;  // 16 warps * 768

    const int tid = threadIdx.x;
    const int NT = 512;

    for (int i = tid; i < 8192; i += NT) sW1[i] = att_W1[i];
    for (int i = tid; i < 4096; i += NT) sMlp[i] = mlp_W1[i];
    for (int i = tid; i < 16384; i += NT) {
        int j = i >> 6, k = i & 63;
        sWihT[k * 256 + j] = W_ih[i];
        sWhhT[k * 256 + j] = W_hh[i];
    }
    if (tid < 64) {
        sb1[tid]  = att_b1[tid];
        sW2[tid]  = att_W2[tid];
        sMb1[tid] = mlp_b1[tid];
        sMW2[tid] = mlp_W2[tid];
    }
    if (tid < 256) sBsum[tid] = b_ih[tid] + b_hh[tid];
    if (tid == 0) { sm[45568] = att_b2[0]; sm[45569] = mlp_b2[0]; }
    __syncthreads();

    const float attB2 = sm[45568];
    const float mlpB2 = sm[45569];
    const int lane = tid & 31;
    const int warpId = tid >> 5;
    float* buf = bufBase + warpId * 768;
    const int j0 = 2 * lane;
    const int mode = g_maskMode;

    const int totalGroups = (P + 3) >> 2;
    const int warpStride = gridDim.x * 16;

    for (int grp = blockIdx.x * 16 + warpId; grp < totalGroups; grp += warpStride) {
        int pid[4];
        #pragma unroll
        for (int q = 0; q < 4; q++) {
            int p = grp * 4 + q;
            pid[q] = p < P ? p : P - 1;
        }

        float2 e0[4], e1[4], e2[4], e3[4], csub[4], psub[4];
        #pragma unroll
        for (int q = 0; q < 4; q++) {
            const int c0 = paths[pid[q] * 4 + 0];
            const int p1 = paths[pid[q] * 4 + 1];
            const int f2 = paths[pid[q] * 4 + 2];
            const int p3 = paths[pid[q] * 4 + 3];
            e0[q] = ld2(company_emb + (size_t)c0 * 64 + j0);
            e1[q] = ld2(patent_emb  + (size_t)p1 * 64 + j0);
            e2[q] = ld2(fp_emb      + (size_t)f2 * 64 + j0);
            e3[q] = ld2(patent_emb  + (size_t)p3 * 64 + j0);

            // company_sub(c0)
            float ax = 0.f, ay = 0.f, cnt = 0.f;
            #pragma unroll
            for (int t = 0; t < 4; t++) {
                if (rdmask(comp_ind_mask, c0 * 4 + t, mode) != 0.f) {
                    float2 v = ld2(ind_emb + (size_t)comp_ind_idx[c0 * 4 + t] * 64 + j0);
                    ax += v.x; ay += v.y; cnt += 1.f;
                }
            }
            #pragma unroll
            for (int t = 0; t < 16; t++) {
                if (rdmask(comp_pat_mask, c0 * 16 + t, mode) != 0.f) {
                    float2 v = ld2(patent_emb + (size_t)comp_pat_idx[c0 * 16 + t] * 64 + j0);
                    ax += v.x; ay += v.y; cnt += 1.f;
                }
            }
            float inv = rcpap(cnt);
            csub[q] = make_float2(e0[q].x + ax * inv, e0[q].y + ay * inv);

            // patent_sub(p3)
            ax = 0.f; ay = 0.f; cnt = 0.f;
            #pragma unroll
            for (int t = 0; t < 2; t++) {
                if (rdmask(pat_fp_mask, p3 * 2 + t, mode) != 0.f) {
                    float2 v = ld2(fp_emb + (size_t)pat_fp_idx[p3 * 2 + t] * 64 + j0);
                    ax += v.x; ay += v.y; cnt += 1.f;
                }
            }
            #pragma unroll
            for (int t = 0; t < 6; t++) {
                if (rdmask(pat_ipc_mask, p3 * 6 + t, mode) != 0.f) {
                    float2 v = ld2(ipc_emb + (size_t)pat_ipc_idx[p3 * 6 + t] * 64 + j0);
                    ax += v.x; ay += v.y; cnt += 1.f;
                }
            }
            #pragma unroll
            for (int t = 0; t < 2; t++) {
                if (rdmask(pat_comp_mask, p3 * 2 + t, mode) != 0.f) {
                    float2 v = ld2(company_emb + (size_t)pat_comp_idx[p3 * 2 + t] * 64 + j0);
                    ax += v.x; ay += v.y; cnt += 1.f;
                }
            }
            inv = rcpap(cnt);
            psub[q] = make_float2(e3[q].x + ax * inv, e3[q].y + ay * inv);
        }

        // Attention fusions: both e1,e2 vs csub (shared), then both vs psub.
        att_fuse_pair(e1, e2, csub, buf, sW1, sb1, sW2, attB2, lane);
        att_fuse_pair(e1, e2, psub, buf, sW1, sb1, sW2, attB2, lane);

        // LSTM over [e0, e1, e2, e3]
        float2 h[4], c[4];
        #pragma unroll
        for (int q = 0; q < 4; q++) { h[q] = make_float2(0.f, 0.f); c[q] = make_float2(0.f, 0.f); }
        lstm_step4(h, c, e0, buf, sWihT, sWhhT, sBsum, lane);
        lstm_step4(h, c, e1, buf, sWihT, sWhhT, sBsum, lane);
        lstm_step4(h, c, e2, buf, sWihT, sWhhT, sBsum, lane);
        lstm_step4(h, c, e3, buf, sWihT, sWhhT, sBsum, lane);

        // MLP head (path-pair packed)
        *reinterpret_cast<float4*>(&buf[8 * lane])     = make_float4(h[0].x, h[1].x, h[2].x, h[3].x);
        *reinterpret_cast<float4*>(&buf[8 * lane + 4]) = make_float4(h[0].y, h[1].y, h[2].y, h[3].y);
        __syncwarp();
        {
            const float bx = sMb1[j0], by = sMb1[j0 + 1];
            uint64_t hx01 = pk2(bx, bx), hx23 = hx01;
            uint64_t hy01 = pk2(by, by), hy23 = hy01;
            #pragma unroll 4
            for (int k = 0; k < 64; k++) {
                ulonglong2 pp = *reinterpret_cast<const ulonglong2*>(&buf[4 * k]);
                float2 w = *reinterpret_cast<const float2*>(&sMlp[(k << 6) + j0]);
                uint64_t wxx = pk2(w.x, w.x);
                uint64_t wyy = pk2(w.y, w.y);
                ffma2(hx01, pp.x, wxx); ffma2(hx23, pp.y, wxx);
                ffma2(hy01, pp.x, wyy); ffma2(hy23, pp.y, wyy);
            }
            float2 a01 = upk2(hx01), a23 = upk2(hx23), b01 = upk2(hy01), b23 = upk2(hy23);
            float hx[4] = {a01.x, a01.y, a23.x, a23.y};
            float hy[4] = {b01.x, b01.y, b23.x, b23.y};
            const float w2x = sMW2[j0], w2y = sMW2[j0 + 1];
            float part[4];
            #pragma unroll
            for (int q = 0; q < 4; q++) {
                float a = fmaxf(hx[q], 0.f);
                float b = fmaxf(hy[q], 0.f);
                part[q] = a * w2x + b * w2y;
            }
            #pragma unroll
            for (int off = 16; off > 0; off >>= 1) {
                #pragma unroll
                for (int q = 0; q < 4; q++) part[q] += __shfl_xor_sync(FULLMASK, part[q], off);
            }
            if (lane == 0) {
                #pragma unroll
                for (int q = 0; q < 4; q++) {
                    int p = grp * 4 + q;
                    if (p < P) out[p] = sigm(part[q] + mlpB2);
                }
            }
        }
        __syncwarp();
    }
}

// ---------------------------------------------------------------------------
extern "C" void kernel_launch(void* const* d_in, const int* in_sizes, int n_in,
                              void* d_out, int out_size)
{
    const int P = in_sizes[0] / 4;
    constexpr size_t SMEM = (size_t)(45584 + 16 * 768) * sizeof(float);  // 231488 B

    cudaFuncSetAttribute(patent_path_kernel,
                         cudaFuncAttributeMaxDynamicSharedMemorySize, (int)SMEM);

    probe_mask_kernel<<<1, 1>>>((const unsigned*)d_in[3]);

    patent_path_kernel<<<148, 512, SMEM>>>(
        (const int*)d_in[0],
        (const int*)d_in[2],  (const char*)d_in[3],
        (const int*)d_in[4],  (const char*)d_in[5],
        (const int*)d_in[6],  (const char*)d_in[7],
        (const int*)d_in[8],  (const char*)d_in[9],
        (const int*)d_in[10], (const char*)d_in[11],
        (const float*)d_in[12], (const float*)d_in[13], (const float*)d_in[14],
        (const float*)d_in[15], (const float*)d_in[16],
        (const float*)d_in[17], (const float*)d_in[18],
        (const float*)d_in[19], (const float*)d_in[20],
        (const float*)d_in[21], (const float*)d_in[22],
        (const float*)d_in[23], (const float*)d_in[24],
        (const float*)d_in[25], (const float*)d_in[26],
        (const float*)d_in[27], (const float*)d_in[28],
        (float*)d_out, P);
}